// round 14
// baseline (speedup 1.0000x reference)
#include <cuda_runtime.h>

#define DIM   4096
#define RANK  32
#define NEDIT 32            // B(4) * 8 edited rows

// ---------------------------------------------------------------------------
// Single kernel, two CTA roles:
//   bids 0..31      : self-contained per-row ReFT edit (hidden in copy wave)
//   bids 32..16415  : one copy CTA per row, edited rows skipped
// __launch_bounds__(256, 4): 64-reg ceiling — enough for the copy path's
// 4-deep float4 batch (proven to fit in 44 regs in R2) while allowing
// 4 CTAs/SM (vs 2 at regs=128 in R13, occ 20.7% -> ~41%+).
// ---------------------------------------------------------------------------
__global__ __launch_bounds__(256, 4) void reft_kernel(
    const float* __restrict__ hs,
    const float* __restrict__ Wsrc_p, const float* __restrict__ bsrc_p,
    const float* __restrict__ Wproj_p,
    const float* __restrict__ Wsrc_s, const float* __restrict__ bsrc_s,
    const float* __restrict__ Wproj_s,
    const int* __restrict__ offsets, const int* __restrict__ seqlens,
    float* __restrict__ out)
{
    const int tid = threadIdx.x;

    if (blockIdx.x >= NEDIT) {
        // ---------------- copy path ----------------
        const int row = blockIdx.x - NEDIT;    // 0..16383
        const int b = row >> 12;
        const int t = row & 4095;
        const int off = offsets[b];
        const int seq = seqlens[b];
        if (((unsigned)(t - off) < 4u) | ((unsigned)(t - (off + seq - 4)) < 4u))
            return;   // edited row: owned by an edit CTA

        const long base = (long)row * DIM;
        const float4* x4 = (const float4*)(hs + base);
        float4*       o4 = (float4*)(out + base);
        #pragma unroll
        for (int k = 0; k < 4; k++) {
            int i = tid + k * 256;
            o4[i] = x4[i];
        }
        return;
    }

    // ---------------- edit path: one CTA per edited row --------------------
    __shared__ float4 xs4[DIM / 4];  // 16 KB
    __shared__ float  dots[2 * RANK];
    __shared__ float  s[RANK];

    const int j = blockIdx.x;        // 0..31
    const int b = j >> 3;
    const int slot = j & 7;
    int pos;
    const float *Wsrc, *bias, *Wproj;
    if (slot < 4) {
        pos = offsets[b] + slot;
        Wsrc = Wsrc_p; bias = bsrc_p; Wproj = Wproj_p;
    } else {
        pos = offsets[b] + seqlens[b] - 8 + slot;
        Wsrc = Wsrc_s; bias = bsrc_s; Wproj = Wproj_s;
    }

    const long base = ((long)b * 4096 + pos) * DIM;
    const float4* x4 = (const float4*)(hs + base);
    #pragma unroll
    for (int k = 0; k < 4; k++) {
        int i = tid + k * 256;
        xs4[i] = x4[i];
    }
    __syncthreads();

    // 64 dots: 8 warps x 8 dots, dual accumulators
    const int warp = tid >> 5;
    const int lane = tid & 31;
    #pragma unroll
    for (int k = 0; k < 8; k++) {
        const int di = warp * 8 + k;       // 0..63
        const float4* W4 = (const float4*)((di < RANK)
                               ? (Wsrc  + (long)di * DIM)
                               : (Wproj + (long)(di - RANK) * DIM));
        float acc0 = 0.f, acc1 = 0.f;
        #pragma unroll 4
        for (int i = lane; i < DIM / 4; i += 64) {
            float4 w0 = W4[i],      xv0 = xs4[i];
            float4 w1 = W4[i + 32], xv1 = xs4[i + 32];
            acc0 += w0.x * xv0.x + w0.y * xv0.y + w0.z * xv0.z + w0.w * xv0.w;
            acc1 += w1.x * xv1.x + w1.y * xv1.y + w1.z * xv1.z + w1.w * xv1.w;
        }
        float acc = acc0 + acc1;
        #pragma unroll
        for (int o = 16; o > 0; o >>= 1)
            acc += __shfl_xor_sync(0xffffffff, acc, o);
        if (lane == 0) dots[di] = acc;
    }
    __syncthreads();

    if (tid < RANK) {
        float src  = dots[tid] + bias[tid];
        float proj = dots[tid + RANK];
        s[tid] = (src > 0.f ? src : 0.f) - proj;
    }
    __syncthreads();

    float4* o4 = (float4*)(out + base);
    #pragma unroll
    for (int k = 0; k < 4; k++) {
        int i = tid + k * 256;
        float4 acc = xs4[i];
        #pragma unroll
        for (int r = 0; r < RANK; r++) {
            float4 w = ((const float4*)(Wproj + (long)r * DIM))[i];
            float sr = s[r];
            acc.x += sr * w.x;
            acc.y += sr * w.y;
            acc.z += sr * w.z;
            acc.w += sr * w.w;
        }
        o4[i] = acc;
    }
}

extern "C" void kernel_launch(void* const* d_in, const int* in_sizes, int n_in,
                              void* d_out, int out_size) {
    const float* hs      = (const float*)d_in[0];
    const float* Wsrc_p  = (const float*)d_in[1];
    const float* bsrc_p  = (const float*)d_in[2];
    const float* Wproj_p = (const float*)d_in[3];
    const float* Wsrc_s  = (const float*)d_in[4];
    const float* bsrc_s  = (const float*)d_in[5];
    const float* Wproj_s = (const float*)d_in[6];
    const int*   offsets = (const int*)d_in[7];
    const int*   seqlens = (const int*)d_in[8];
    float* out = (float*)d_out;

    const int nrows = out_size / DIM;      // 16384
    reft_kernel<<<NEDIT + nrows, 256>>>(
        hs, Wsrc_p, bsrc_p, Wproj_p, Wsrc_s, bsrc_s, Wproj_s,
        offsets, seqlens, out);
}